// round 15
// baseline (speedup 1.0000x reference)
#include <cuda_runtime.h>

// ---------------------------------------------------------------------------
// ChordProgressionLoss v15 — merge of all bench-validated winners.
//   * PAIR loop: 2 consecutive 29-row chunks per iteration = 4 front-batched
//     LDG.128 (bench: 4-load variants 14.24us vs 2-load 15.1us).
//   * guard-free interior (pair safe iff (2k+1)*29 <= T-32); <=5 tail chunks
//     distributed one-per-warp with full guards.
//   * 768 threads x 2 blocks/SM (48 warps/SM, 42-reg budget, no spills).
//   * scalar magic-add masks, PRMT jaccard bytes, 3 shfl + dp4a windows,
//     integer max, fixed-point sim; exact -> deterministic atomics.
// ---------------------------------------------------------------------------

#define NBLK 296
#define THREADS 768
#define WPB 24
#define NW (NBLK * WPB)          // 7104 warps

__device__ unsigned long long g_simSlots[32];
__device__ unsigned long long g_penSlots[32];
__device__ unsigned int       g_count = 0;

__device__ __forceinline__ unsigned pcbit(float f) {
    unsigned b1 = __float_as_uint(f + 12582912.0f);          // low bits = iv
    float t = fmaf(f, 0.0833333358f, -0.45833334f);
    unsigned b2 = __float_as_uint(t + 12582912.0f);          // low bits = iv/12
    return 1u << ((b1 - 12u * b2) & 31u);                    // low5 = iv%12
}
__device__ __forceinline__ unsigned pcmask(float4 v) {
    return pcbit(v.x) | pcbit(v.y) | pcbit(v.z) | pcbit(v.w);
}

__device__ __forceinline__ void chunkMath(
    unsigned pm, unsigned tm, bool simOwn, bool penOwn,
    const unsigned* __restrict__ sT60, const uint2* __restrict__ sSim,
    unsigned long long& simAcc, unsigned& penAcc)
{
    int p  = __popc(pm);                      // 1..4
    int q  = __popc(tm);
    int it = __popc(pm & tm);

    uint2 ra = sSim[p * 4 + q];
    if (simOwn) simAcc += (unsigned long long)((unsigned)it * ra.x + ra.y);

    unsigned Tp = sT60[p];
    unsigned iM0 = __popc(pm & 0x091u), iM1 = __popc(pm & 0x221u), iM2 = __popc(pm & 0x884u);
    unsigned im0 = __popc(pm & 0x089u), im1 = __popc(pm & 0x121u), im2 = __popc(pm & 0x484u);
    unsigned selP = iM0 | (im0 << 4) | (iM2 << 8) | (im2 << 12);
    unsigned selQ = iM1 | (im1 << 4);
    unsigned P = __byte_perm(Tp, 0, selP);    // {tM0, tm0, tM2, tm2}
    unsigned Q = __byte_perm(Tp, 0, selQ);    // {tM1, tm1, -, -}

    unsigned Q1 = __shfl_down_sync(0xffffffffu, Q, 1);
    unsigned P2 = __shfl_down_sync(0xffffffffu, P, 2);
    unsigned P3 = __shfl_down_sync(0xffffffffu, P, 3);

    unsigned v1 = __byte_perm(P,  Q1, 0x0040);
    unsigned v2 = __byte_perm(P2, P3, 0x0042);
    unsigned majW = __byte_perm(v1, v2, 0x5410);
    unsigned w1 = __byte_perm(P,  Q1, 0x0051);
    unsigned w2 = __byte_perm(P2, P3, 0x0053);
    unsigned minW = __byte_perm(w1, w2, 0x5410);

    unsigned SM = __dp4a(majW, 0x01010101u, 0u);
    unsigned Sm = __dp4a(minW, 0x01010101u, 0u);
    if (penOwn) penAcc += (SM > Sm) ? SM : Sm;   // 240*(1-min(maj,mino))
}

__global__ __launch_bounds__(THREADS, 2) void chord_fused(
    const float4* __restrict__ pred, const float4* __restrict__ targ,
    float* __restrict__ out, int T, int nPairsFast, int nChunks)
{
    __shared__ unsigned sT60[5];
    __shared__ uint2    sSim[21];
    __shared__ unsigned long long redS[WPB], redP[WPB];
    __shared__ bool     sLast;

    const int tid = threadIdx.x;
    if (tid < 5) {
        int p = tid; unsigned w = 0;
        for (int i = 0; i < 4; i++) {
            int dnm = p + 3 - i;
            unsigned t = (dnm > 0) ? (unsigned)((60 * i) / dnm) : 0u;
            w |= (t & 0xFFu) << (8 * i);
        }
        sT60[p] = w;
    }
    if (tid < 16) {
        int p = (tid >> 2) + 1, q = (tid & 3) + 1;
        double r = 1.0 / (((double)p + 12e-6) * ((double)q + 12e-6));
        unsigned R30 = (unsigned)__double2ll_rn(r * 1073741824.0);
        unsigned A30 = (unsigned)__double2ll_rn((1e-6 * (p + q) + 1.2e-11) * r * 1073741824.0);
        sSim[p * 4 + q] = make_uint2(R30, A30);
    }
    __syncthreads();

    const int lane = tid & 31;
    const int wid  = tid >> 5;
    const bool laneOwn = (lane < 29);
    const int  W = blockIdx.x * WPB + wid;      // global warp id

    unsigned long long simAcc = 0ull;
    unsigned penAcc = 0u;

    // ---- interior: pairs of chunks, 4 LDG.128 front-batched, no guards ----
    {
        const float4* pp = pred + ((long long)W * 58 + lane);
        const float4* tp = targ + ((long long)W * 58 + lane);
        const long long step = (long long)NW * 58;
        int k = W;
        #pragma unroll 1
        while (k < nPairsFast) {
            float4 pA = pp[0],  tA = tp[0];      // chunk 2k
            float4 pB = pp[29], tB = tp[29];     // chunk 2k+1
            unsigned pmA = pcmask(pA), tmA = pcmask(tA);
            unsigned pmB = pcmask(pB), tmB = pcmask(tB);
            chunkMath(pmA, tmA, laneOwn, laneOwn, sT60, sSim, simAcc, penAcc);
            chunkMath(pmB, tmB, laneOwn, laneOwn, sT60, sSim, simAcc, penAcc);
            pp += step; tp += step;
            k += NW;
        }
    }

    // ---- tail: chunks [2*nPairsFast, nChunks), one per warp, full guards ----
    {
        const int u = 2 * nPairsFast + W;       // warp W takes tail chunk u
        if (u < nChunks) {
            const int rMax = (T > 0) ? (T - 1) : 0;
            const int lastWin = T - 4;
            const int r = u * 29 + lane;
            const int c = (r < rMax) ? r : rMax;
            float4 pv = pred[c];
            float4 tv = targ[c];
            unsigned pm = pcmask(pv);
            unsigned tm = pcmask(tv);
            chunkMath(pm, tm, laneOwn && (r < T), laneOwn && (r <= lastWin),
                      sT60, sSim, simAcc, penAcc);
        }
    }

    // warp reduction (exact integers -> order-independent)
    unsigned long long penW = (unsigned long long)penAcc;
    #pragma unroll
    for (int o = 16; o; o >>= 1) {
        simAcc += __shfl_xor_sync(0xffffffffu, simAcc, o);
        penW   += __shfl_xor_sync(0xffffffffu, penW,   o);
    }
    if (lane == 0) { redS[wid] = simAcc; redP[wid] = penW; }
    __syncthreads();

    if (wid == 0) {
        unsigned long long s = (lane < WPB) ? redS[lane] : 0ull;
        unsigned long long p = (lane < WPB) ? redP[lane] : 0ull;
        #pragma unroll
        for (int o = 16; o; o >>= 1) {
            s += __shfl_xor_sync(0xffffffffu, s, o);
            p += __shfl_xor_sync(0xffffffffu, p, o);
        }
        if (lane == 0) {
            int slot = blockIdx.x & 31;
            atomicAdd(&g_simSlots[slot], s);
            atomicAdd(&g_penSlots[slot], p);
            __threadfence();
            sLast = (atomicAdd(&g_count, 1u) == gridDim.x - 1);
        }
    }
    __syncthreads();

    if (sLast && wid == 0) {
        __threadfence();
        unsigned long long s = *(volatile unsigned long long*)&g_simSlots[lane];
        unsigned long long p = *(volatile unsigned long long*)&g_penSlots[lane];
        #pragma unroll
        for (int o = 16; o; o >>= 1) {
            s += __shfl_xor_sync(0xffffffffu, s, o);
            p += __shfl_xor_sync(0xffffffffu, p, o);
        }
        if (lane == 0) {
            double simMean = ((double)s * (1.0 / 1073741824.0)) / (double)T;
            long long nWin = (long long)T - 3;
            double pen = (nWin > 0) ? (0.5 - (double)p / (480.0 * (double)nWin)) : 0.0;
            out[0] = (float)((1.0 - simMean) + pen);
        }
        g_simSlots[lane] = 0ull;   // self-reset for graph replay
        g_penSlots[lane] = 0ull;
        if (lane == 0) g_count = 0;
    }
}

extern "C" void kernel_launch(void* const* d_in, const int* in_sizes, int n_in,
                              void* d_out, int out_size)
{
    const float4* pred = (const float4*)d_in[0];
    const float4* targ = (const float4*)d_in[1];
    int T1 = in_sizes[0] / 4;
    int T2 = in_sizes[1] / 4;
    int T = (T1 < T2) ? T1 : T2;

    int nChunks = (T + 28) / 29;
    if (nChunks < 1) nChunks = 1;
    // pair k (chunks 2k, 2k+1) is guard-free iff (2k+1)*29 <= T-32
    // (second chunk's loads reach (2k+1)*29+31, windows reach (2k+1)*29+31)
    int nPairsFast = 0;
    if (T >= 61) {
        long long m = ((long long)T - 61) / 58 + 1;   // #pairs with (2k+1)*29+31 <= T-1... conservative
        // require (2k+1)*29 + 31 <= T-1  ->  58k <= T - 61
        nPairsFast = (int)m;
    }
    if (2 * nPairsFast > nChunks) nPairsFast = nChunks / 2;

    chord_fused<<<NBLK, THREADS>>>(pred, targ, (float*)d_out, T, nPairsFast, nChunks);
}

// round 16
// speedup vs baseline: 1.0382x; 1.0382x over previous
#include <cuda_runtime.h>

// ---------------------------------------------------------------------------
// ChordProgressionLoss v16 — R15 compute + two-level arrival tree.
// Diagnosis: 296 same-address g_count atomics serialize (~30cyc each) into a
// ~4.5us tail after balanced compute. Fix: level-1 arrival on 32 parallel
// counters (bid&31), only the per-slot-last block touches the single level-2
// counter (32 serialized RMWs instead of 296).
// Compute identical to R15: pair loop (4 front-batched LDG.128), guard-free
// interior, scalar magic masks, PRMT jaccard bytes, 3 shfl + dp4a windows,
// integer max, fixed-point sim. Exact integers -> deterministic atomics.
// ---------------------------------------------------------------------------

#define NBLK 296
#define THREADS 768
#define WPB 24
#define NW (NBLK * WPB)          // 7104 warps

__device__ unsigned long long g_simSlots[32];
__device__ unsigned long long g_penSlots[32];
__device__ unsigned int       g_cnt1[32];
__device__ unsigned int       g_cnt2 = 0;

__device__ __forceinline__ unsigned pcbit(float f) {
    unsigned b1 = __float_as_uint(f + 12582912.0f);          // low bits = iv
    float t = fmaf(f, 0.0833333358f, -0.45833334f);
    unsigned b2 = __float_as_uint(t + 12582912.0f);          // low bits = iv/12
    return 1u << ((b1 - 12u * b2) & 31u);                    // low5 = iv%12
}
__device__ __forceinline__ unsigned pcmask(float4 v) {
    return pcbit(v.x) | pcbit(v.y) | pcbit(v.z) | pcbit(v.w);
}

__device__ __forceinline__ void chunkMath(
    unsigned pm, unsigned tm, bool simOwn, bool penOwn,
    const unsigned* __restrict__ sT60, const uint2* __restrict__ sSim,
    unsigned long long& simAcc, unsigned& penAcc)
{
    int p  = __popc(pm);                      // 1..4
    int q  = __popc(tm);
    int it = __popc(pm & tm);

    uint2 ra = sSim[p * 4 + q];
    if (simOwn) simAcc += (unsigned long long)((unsigned)it * ra.x + ra.y);

    unsigned Tp = sT60[p];
    unsigned iM0 = __popc(pm & 0x091u), iM1 = __popc(pm & 0x221u), iM2 = __popc(pm & 0x884u);
    unsigned im0 = __popc(pm & 0x089u), im1 = __popc(pm & 0x121u), im2 = __popc(pm & 0x484u);
    unsigned selP = iM0 | (im0 << 4) | (iM2 << 8) | (im2 << 12);
    unsigned selQ = iM1 | (im1 << 4);
    unsigned P = __byte_perm(Tp, 0, selP);    // {tM0, tm0, tM2, tm2}
    unsigned Q = __byte_perm(Tp, 0, selQ);    // {tM1, tm1, -, -}

    unsigned Q1 = __shfl_down_sync(0xffffffffu, Q, 1);
    unsigned P2 = __shfl_down_sync(0xffffffffu, P, 2);
    unsigned P3 = __shfl_down_sync(0xffffffffu, P, 3);

    unsigned v1 = __byte_perm(P,  Q1, 0x0040);
    unsigned v2 = __byte_perm(P2, P3, 0x0042);
    unsigned majW = __byte_perm(v1, v2, 0x5410);
    unsigned w1 = __byte_perm(P,  Q1, 0x0051);
    unsigned w2 = __byte_perm(P2, P3, 0x0053);
    unsigned minW = __byte_perm(w1, w2, 0x5410);

    unsigned SM = __dp4a(majW, 0x01010101u, 0u);
    unsigned Sm = __dp4a(minW, 0x01010101u, 0u);
    if (penOwn) penAcc += (SM > Sm) ? SM : Sm;   // 240*(1-min(maj,mino))
}

__global__ __launch_bounds__(THREADS, 2) void chord_fused(
    const float4* __restrict__ pred, const float4* __restrict__ targ,
    float* __restrict__ out, int T, int nPairsFast, int nChunks)
{
    __shared__ unsigned sT60[5];
    __shared__ uint2    sSim[21];
    __shared__ unsigned long long redS[WPB], redP[WPB];
    __shared__ bool     sLast;

    const int tid = threadIdx.x;
    if (tid < 5) {
        int p = tid; unsigned w = 0;
        for (int i = 0; i < 4; i++) {
            int dnm = p + 3 - i;
            unsigned t = (dnm > 0) ? (unsigned)((60 * i) / dnm) : 0u;
            w |= (t & 0xFFu) << (8 * i);
        }
        sT60[p] = w;
    }
    if (tid < 16) {
        int p = (tid >> 2) + 1, q = (tid & 3) + 1;
        double r = 1.0 / (((double)p + 12e-6) * ((double)q + 12e-6));
        unsigned R30 = (unsigned)__double2ll_rn(r * 1073741824.0);
        unsigned A30 = (unsigned)__double2ll_rn((1e-6 * (p + q) + 1.2e-11) * r * 1073741824.0);
        sSim[p * 4 + q] = make_uint2(R30, A30);
    }
    __syncthreads();

    const int lane = tid & 31;
    const int wid  = tid >> 5;
    const bool laneOwn = (lane < 29);
    const int  W = blockIdx.x * WPB + wid;      // global warp id

    unsigned long long simAcc = 0ull;
    unsigned penAcc = 0u;

    // ---- interior: chunk pairs, 4 LDG.128 front-batched, no guards ----
    {
        const float4* pp = pred + ((long long)W * 58 + lane);
        const float4* tp = targ + ((long long)W * 58 + lane);
        const long long step = (long long)NW * 58;
        int k = W;
        #pragma unroll 1
        while (k < nPairsFast) {
            float4 pA = pp[0],  tA = tp[0];      // chunk 2k
            float4 pB = pp[29], tB = tp[29];     // chunk 2k+1
            unsigned pmA = pcmask(pA), tmA = pcmask(tA);
            unsigned pmB = pcmask(pB), tmB = pcmask(tB);
            chunkMath(pmA, tmA, laneOwn, laneOwn, sT60, sSim, simAcc, penAcc);
            chunkMath(pmB, tmB, laneOwn, laneOwn, sT60, sSim, simAcc, penAcc);
            pp += step; tp += step;
            k += NW;
        }
    }

    // ---- tail: chunks [2*nPairsFast, nChunks), one per warp, full guards ----
    {
        const int u = 2 * nPairsFast + W;
        if (u < nChunks) {
            const int rMax = (T > 0) ? (T - 1) : 0;
            const int lastWin = T - 4;
            const int r = u * 29 + lane;
            const int c = (r < rMax) ? r : rMax;
            float4 pv = pred[c];
            float4 tv = targ[c];
            unsigned pm = pcmask(pv);
            unsigned tm = pcmask(tv);
            chunkMath(pm, tm, laneOwn && (r < T), laneOwn && (r <= lastWin),
                      sT60, sSim, simAcc, penAcc);
        }
    }

    // warp reduction (exact integers -> order-independent)
    unsigned long long penW = (unsigned long long)penAcc;
    #pragma unroll
    for (int o = 16; o; o >>= 1) {
        simAcc += __shfl_xor_sync(0xffffffffu, simAcc, o);
        penW   += __shfl_xor_sync(0xffffffffu, penW,   o);
    }
    if (lane == 0) { redS[wid] = simAcc; redP[wid] = penW; }
    __syncthreads();

    if (wid == 0) {
        unsigned long long s = (lane < WPB) ? redS[lane] : 0ull;
        unsigned long long p = (lane < WPB) ? redP[lane] : 0ull;
        #pragma unroll
        for (int o = 16; o; o >>= 1) {
            s += __shfl_xor_sync(0xffffffffu, s, o);
            p += __shfl_xor_sync(0xffffffffu, p, o);
        }
        if (lane == 0) {
            const int slot = blockIdx.x & 31;
            atomicAdd(&g_simSlots[slot], s);
            atomicAdd(&g_penSlots[slot], p);
            __threadfence();
            // two-level arrival: 32 parallel slot counters, then 1 counter
            // slots 0..7 expect 10 blocks, slots 8..31 expect 9 (296=9*32+8)
            const unsigned expect = 9u + (slot < 8 ? 1u : 0u);
            bool slotLast = (atomicAdd(&g_cnt1[slot], 1u) == expect - 1u);
            bool last = false;
            if (slotLast) {
                __threadfence();
                last = (atomicAdd(&g_cnt2, 1u) == 31u);
            }
            sLast = last;
        }
    }
    __syncthreads();

    if (sLast && wid == 0) {
        __threadfence();
        unsigned long long s = *(volatile unsigned long long*)&g_simSlots[lane];
        unsigned long long p = *(volatile unsigned long long*)&g_penSlots[lane];
        #pragma unroll
        for (int o = 16; o; o >>= 1) {
            s += __shfl_xor_sync(0xffffffffu, s, o);
            p += __shfl_xor_sync(0xffffffffu, p, o);
        }
        if (lane == 0) {
            double simMean = ((double)s * (1.0 / 1073741824.0)) / (double)T;
            long long nWin = (long long)T - 3;
            double pen = (nWin > 0) ? (0.5 - (double)p / (480.0 * (double)nWin)) : 0.0;
            out[0] = (float)((1.0 - simMean) + pen);
        }
        g_simSlots[lane] = 0ull;   // self-reset for graph replay
        g_penSlots[lane] = 0ull;
        g_cnt1[lane] = 0u;
        if (lane == 0) g_cnt2 = 0u;
    }
}

extern "C" void kernel_launch(void* const* d_in, const int* in_sizes, int n_in,
                              void* d_out, int out_size)
{
    const float4* pred = (const float4*)d_in[0];
    const float4* targ = (const float4*)d_in[1];
    int T1 = in_sizes[0] / 4;
    int T2 = in_sizes[1] / 4;
    int T = (T1 < T2) ? T1 : T2;

    int nChunks = (T + 28) / 29;
    if (nChunks < 1) nChunks = 1;
    // pair k (chunks 2k,2k+1) guard-free iff (2k+1)*29 + 31 <= T-1
    int nPairsFast = 0;
    if (T >= 61) nPairsFast = (int)(((long long)T - 61) / 58 + 1);
    if (2 * nPairsFast > nChunks) nPairsFast = nChunks / 2;

    chord_fused<<<NBLK, THREADS>>>(pred, targ, (float*)d_out, T, nPairsFast, nChunks);
}

// round 17
// speedup vs baseline: 1.2225x; 1.1775x over previous
#include <cuda_runtime.h>

// ---------------------------------------------------------------------------
// ChordProgressionLoss v17 — byte-identical resubmission of R9 (best bench:
// 14.24us) as a confirmation probe. 16 rounds of evidence: all structural
// variants land in a 14.2-15.6us band; R9's config (768x2, 58-row grid-stride
// units with 4 front-batched LDG.128, f32x2 magic masks, PRMT jaccard bytes,
// 3-shuffle windows, integer/fixed-point accumulators, 296-block atomic
// epilogue) holds the band minimum. If this reproduces ~14.2, it is the
// final answer; if ~15.1, the band is noise and all variants are equivalent.
// ---------------------------------------------------------------------------

#define NBLK 296
#define THREADS 768
#define WPB 24

__device__ unsigned long long g_simSlots[32];
__device__ unsigned long long g_penSlots[32];
__device__ unsigned int       g_count = 0;

#define MAGIC2  0x4B4000004B400000ULL
#define INV12_2 0x3DAAAAAB3DAAAAABULL
#define BIAS2   0xBEEAAAABBEEAAAABULL

__device__ __forceinline__ unsigned pcmask(float4 v) {
    unsigned long long dxy, dzw, b1xy, b1zw, t, b2xy, b2zw;
    asm("mov.b64 %0, {%1,%2};" : "=l"(dxy) : "f"(v.x), "f"(v.y));
    asm("mov.b64 %0, {%1,%2};" : "=l"(dzw) : "f"(v.z), "f"(v.w));
    asm("add.rn.f32x2 %0, %1, %2;" : "=l"(b1xy) : "l"(dxy), "l"(MAGIC2));
    asm("add.rn.f32x2 %0, %1, %2;" : "=l"(b1zw) : "l"(dzw), "l"(MAGIC2));
    asm("fma.rn.f32x2 %0, %1, %2, %3;" : "=l"(t) : "l"(dxy), "l"(INV12_2), "l"(BIAS2));
    asm("add.rn.f32x2 %0, %1, %2;" : "=l"(b2xy) : "l"(t), "l"(MAGIC2));
    asm("fma.rn.f32x2 %0, %1, %2, %3;" : "=l"(t) : "l"(dzw), "l"(INV12_2), "l"(BIAS2));
    asm("add.rn.f32x2 %0, %1, %2;" : "=l"(b2zw) : "l"(t), "l"(MAGIC2));
    unsigned a0, a1, a2, a3, q0, q1, q2, q3;
    asm("mov.b64 {%0,%1}, %2;" : "=r"(a0), "=r"(a1) : "l"(b1xy));
    asm("mov.b64 {%0,%1}, %2;" : "=r"(a2), "=r"(a3) : "l"(b1zw));
    asm("mov.b64 {%0,%1}, %2;" : "=r"(q0), "=r"(q1) : "l"(b2xy));
    asm("mov.b64 {%0,%1}, %2;" : "=r"(q2), "=r"(q3) : "l"(b2zw));
    return (1u << ((a0 - 12u * q0) & 31u))
         | (1u << ((a1 - 12u * q1) & 31u))
         | (1u << ((a2 - 12u * q2) & 31u))
         | (1u << ((a3 - 12u * q3) & 31u));
}

__device__ __forceinline__ void doChunk(
    unsigned pm, unsigned tm, int r, int T, bool laneOwn,
    const unsigned* __restrict__ sT60, const uint2* __restrict__ sSim,
    unsigned long long& simAcc, unsigned& penAcc)
{
    int p  = __popc(pm);                      // 1..4
    int q  = __popc(tm);
    int it = __popc(pm & tm);

    uint2 ra = sSim[p * 4 + q];
    if (laneOwn && (r < T)) simAcc += (unsigned long long)((unsigned)it * ra.x + ra.y);

    unsigned Tp = sT60[p];
    unsigned iM0 = __popc(pm & 0x091u), iM1 = __popc(pm & 0x221u), iM2 = __popc(pm & 0x884u);
    unsigned im0 = __popc(pm & 0x089u), im1 = __popc(pm & 0x121u), im2 = __popc(pm & 0x484u);
    unsigned selP = iM0 | (im0 << 4) | (iM2 << 8) | (im2 << 12);
    unsigned selQ = iM1 | (im1 << 4);
    unsigned P = __byte_perm(Tp, 0, selP);    // {tM0, tm0, tM2, tm2}
    unsigned Q = __byte_perm(Tp, 0, selQ);    // {tM1, tm1, -, -}

    unsigned Q1 = __shfl_down_sync(0xffffffffu, Q, 1);
    unsigned P2 = __shfl_down_sync(0xffffffffu, P, 2);
    unsigned P3 = __shfl_down_sync(0xffffffffu, P, 3);

    unsigned v1 = __byte_perm(P,  Q1, 0x0040);
    unsigned v2 = __byte_perm(P2, P3, 0x0042);
    unsigned majW = __byte_perm(v1, v2, 0x5410);
    unsigned w1 = __byte_perm(P,  Q1, 0x0051);
    unsigned w2 = __byte_perm(P2, P3, 0x0053);
    unsigned minW = __byte_perm(w1, w2, 0x5410);

    unsigned SM = __dp4a(majW, 0x01010101u, 0u);
    unsigned Sm = __dp4a(minW, 0x01010101u, 0u);
    if (laneOwn && (r <= T - 4)) penAcc += (SM > Sm) ? SM : Sm;   // 240*(1-min)
}

__global__ __launch_bounds__(THREADS, 2) void chord_fused(
    const float4* __restrict__ pred, const float4* __restrict__ targ,
    float* __restrict__ out, int T, int nUnits)
{
    __shared__ unsigned sT60[5];
    __shared__ uint2    sSim[21];
    __shared__ unsigned long long redS[WPB], redP[WPB];
    __shared__ bool     sLast;

    const int tid = threadIdx.x;
    if (tid < 5) {
        int p = tid; unsigned w = 0;
        for (int i = 0; i < 4; i++) {
            int dnm = p + 3 - i;
            unsigned t = (dnm > 0) ? (unsigned)((60 * i) / dnm) : 0u;
            w |= (t & 0xFFu) << (8 * i);
        }
        sT60[p] = w;
    }
    if (tid < 16) {
        int p = (tid >> 2) + 1, q = (tid & 3) + 1;
        double r = 1.0 / (((double)p + 12e-6) * ((double)q + 12e-6));
        unsigned R30 = (unsigned)__double2ll_rn(r * 1073741824.0);
        unsigned A30 = (unsigned)__double2ll_rn((1e-6 * (p + q) + 1.2e-11) * r * 1073741824.0);
        sSim[p * 4 + q] = make_uint2(R30, A30);
    }
    __syncthreads();

    const int lane = tid & 31;
    const int wid  = tid >> 5;
    const bool laneOwn = (lane < 29);

    unsigned long long simAcc = 0ull;
    unsigned penAcc = 0u;
    const int rMax = (T > 0) ? (T - 1) : 0;

    for (int u = blockIdx.x * WPB + wid; u < nUnits; u += gridDim.x * WPB) {
        const int base = u * 58;
        const int rA = base + lane;
        const int rB = base + 29 + lane;
        const int cA = (rA < rMax) ? rA : rMax;     // clamp: branchless loads
        const int cB = (rB < rMax) ? rB : rMax;
        float4 pA = pred[cA], tA = targ[cA];        // 4x LDG.128 batched
        float4 pB = pred[cB], tB = targ[cB];

        // masks immediately: float4s die here (low register liveness)
        unsigned pmA = pcmask(pA), tmA = pcmask(tA);
        unsigned pmB = pcmask(pB), tmB = pcmask(tB);

        doChunk(pmA, tmA, rA, T, laneOwn, sT60, sSim, simAcc, penAcc);
        doChunk(pmB, tmB, rB, T, laneOwn, sT60, sSim, simAcc, penAcc);
    }

    // warp reduction (exact integers -> order-independent)
    unsigned long long penW = (unsigned long long)penAcc;
    #pragma unroll
    for (int o = 16; o; o >>= 1) {
        simAcc += __shfl_xor_sync(0xffffffffu, simAcc, o);
        penW   += __shfl_xor_sync(0xffffffffu, penW,   o);
    }
    if (lane == 0) { redS[wid] = simAcc; redP[wid] = penW; }
    __syncthreads();

    if (wid == 0) {
        unsigned long long s = (lane < WPB) ? redS[lane] : 0ull;
        unsigned long long p = (lane < WPB) ? redP[lane] : 0ull;
        #pragma unroll
        for (int o = 16; o; o >>= 1) {
            s += __shfl_xor_sync(0xffffffffu, s, o);
            p += __shfl_xor_sync(0xffffffffu, p, o);
        }
        if (lane == 0) {
            int slot = blockIdx.x & 31;
            atomicAdd(&g_simSlots[slot], s);
            atomicAdd(&g_penSlots[slot], p);
            __threadfence();
            sLast = (atomicAdd(&g_count, 1u) == gridDim.x - 1);
        }
    }
    __syncthreads();

    if (sLast && wid == 0) {
        __threadfence();
        unsigned long long s = *(volatile unsigned long long*)&g_simSlots[lane];
        unsigned long long p = *(volatile unsigned long long*)&g_penSlots[lane];
        #pragma unroll
        for (int o = 16; o; o >>= 1) {
            s += __shfl_xor_sync(0xffffffffu, s, o);
            p += __shfl_xor_sync(0xffffffffu, p, o);
        }
        if (lane == 0) {
            double simMean = ((double)s * (1.0 / 1073741824.0)) / (double)T;
            long long nWin = (long long)T - 3;
            double pen = (nWin > 0) ? (0.5 - (double)p / (480.0 * (double)nWin)) : 0.0;
            out[0] = (float)((1.0 - simMean) + pen);
        }
        g_simSlots[lane] = 0ull;   // self-reset for graph replay
        g_penSlots[lane] = 0ull;
        if (lane == 0) g_count = 0;
    }
}

extern "C" void kernel_launch(void* const* d_in, const int* in_sizes, int n_in,
                              void* d_out, int out_size)
{
    const float4* pred = (const float4*)d_in[0];
    const float4* targ = (const float4*)d_in[1];
    int T1 = in_sizes[0] / 4;
    int T2 = in_sizes[1] / 4;
    int T = (T1 < T2) ? T1 : T2;

    int nUnits = (T + 57) / 58;
    if (nUnits < 1) nUnits = 1;
    int blocks = (nUnits + WPB - 1) / WPB;
    if (blocks > NBLK) blocks = NBLK;

    chord_fused<<<blocks, THREADS>>>(pred, targ, (float*)d_out, T, nUnits);
}